// round 10
// baseline (speedup 1.0000x reference)
#include <cuda_runtime.h>
#include <cuda_bf16.h>

#define MAX_RANKS (1 << 20)

// Zero is the valid initial state for ALL of these (module load zeroes them;
// k_main/k_last restore zeros each call, so graph replays are self-consistent).
__device__ int2  g_meta[MAX_RANKS];     // .x = count, .y = max(N - i) over points (first = N - y)
__device__ int4  g_info[MAX_RANKS];     // {count, first, g_pred(-1 none), L_pred}
__device__ int   g_worklist[MAX_RANKS];
__device__ int   g_wcount;
__device__ int   g_maxrank;
__device__ float g_T[256];

// hot region = output rows reachable by geom = c0 + c1*W + c2*H + c3
__device__ __forceinline__ long hot_bound(int B, int D, int H, int W, int C4, long n4) {
    long gmax = (long)(W - 1) + (long)(H - 1) * W + (long)(D - 1) * H + (B - 1);
    long hot = (gmax + 1) * C4;
    return hot < n4 ? hot : n4;
}

// ---------------------------------------------------------------- pass A: histogram + first + worklist + maxrank
__global__ void k_hist(const int4* __restrict__ coords, int N,
                       const int* __restrict__ Bp, const int* __restrict__ Dp,
                       const int* __restrict__ Wp) {
    int i = blockIdx.x * blockDim.x + threadIdx.x;
    int B = *Bp, D = *Dp, W = *Wp;
    int s2 = B, s1 = D * B, s0 = W * s1;
    int myrank = 0;
    if (i < N) {
        int4 c = __ldcs(&coords[i]);
        int rank = c.x * s0 + c.y * s1 + c.z * s2 + c.w;
        myrank = rank;
        int old = atomicAdd(&g_meta[rank].x, 1);
        if (old == 0) {
            int pos = atomicAdd(&g_wcount, 1);
            g_worklist[pos] = rank;
        }
        atomicMax(&g_meta[rank].y, N - i);    // first = N - max
    }
    __shared__ int sm[256];
    sm[threadIdx.x] = myrank;
    __syncthreads();
    for (int off = 128; off > 0; off >>= 1) {
        if (threadIdx.x < off) sm[threadIdx.x] = max(sm[threadIdx.x], sm[threadIdx.x + off]);
        __syncthreads();
    }
    if (threadIdx.x == 0) atomicMax(&g_maxrank, sm[0]);
}

// ---------------------------------------------------------------- prep: per-rank fused info + HOT zero (L2-resident into k_main)
__global__ void k_prep(int N,
                       const int* __restrict__ Bp, const int* __restrict__ Dp,
                       const int* __restrict__ Hp, const int* __restrict__ Wp,
                       float4* __restrict__ out4z, long n4, int C4) {
    int w = blockIdx.x * blockDim.x + threadIdx.x;
    int B = *Bp, D = *Dp, H = *Hp, W = *Wp;

    long hot = hot_bound(B, D, H, W, C4, n4);
    long zstride = (long)gridDim.x * blockDim.x;
    for (long z = w; z < hot; z += zstride)
        out4z[z] = make_float4(0.f, 0.f, 0.f, 0.f);

    if (w >= g_wcount) return;
    int j = g_worklist[w];

    int s2 = B, s1 = D * B, s0 = W * s1;
    int2 mj = g_meta[j];
    int first = N - mj.y;

    int p = j - 1;
    int Lp = 0;
    while (p >= 0) {
        Lp = g_meta[p].x;
        if (Lp != 0) break;
        p--;
    }
    int gp = -1;
    if (p >= 0) {
        int d0 = p / s0; int rr = p - d0 * s0;
        int d1 = rr / s1; rr -= d1 * s1;
        int d2 = rr / s2; int d3 = rr - d2 * s2;
        gp = d0 + d1 * W + d2 * H + d3;
    }
    g_info[j] = make_int4(mj.x, first, gp, Lp);
}

// ---------------------------------------------------------------- main streaming pass
// side jobs (ride in spare bw): clean g_meta to zeros, cold-zero the output tail.
#define KB 16
#define ROWS (16 * KB)
#define TPB 320
__global__ void k_main(const float4* __restrict__ feats4, const int4* __restrict__ coords,
                       float4* __restrict__ out4, int N, int C4, long n4,
                       const int* __restrict__ Bp, const int* __restrict__ Dp,
                       const int* __restrict__ Hp, const int* __restrict__ Wp) {
    __shared__ int2   desc[ROWS];        // {target geom or -1, L}
    __shared__ float4 smr[16][64];

    int tx = threadIdx.x;          // channel chunk (0..C4-1)
    int ty = threadIdx.y;          // row-in-tile (0..15)
    int lin = ty * C4 + tx;
    int base = blockIdx.x * ROWS;
    int maxr = g_maxrank;

    int B = *Bp, D = *Dp, H = *Hp, W = *Wp;
    int s2 = B, s1 = D * B, s0 = W * s1;

    // ---- side job 1: restore g_meta zeros for next replay (nobody reads it here)
    long gtid = (long)blockIdx.x * TPB + lin;
    long gstride = (long)gridDim.x * TPB;
    for (long i = gtid; i < MAX_RANKS; i += gstride)
        g_meta[i] = make_int2(0, 0);

    // ---- side job 2: cold-zero output tail (never touched by atomics)
    {
        long hot = hot_bound(B, D, H, W, C4, n4);
        float4 zero = make_float4(0.f, 0.f, 0.f, 0.f);
        for (long z = hot + gtid; z < n4; z += gstride)
            __stcs(&out4[z], zero);
    }

    // ---- phase A: per-row metadata -> smem
    if (lin < ROWS) {
        int row = base + lin;
        int2 d = make_int2(-1, 0);
        if (row < N) {
            int4 c = __ldcs(&coords[row]);
            int rank = c.x * s0 + c.y * s1 + c.z * s2 + c.w;
            int4 info = g_info[rank];
            if (row == info.y) {                 // first point of its rank
                if (info.z >= 0) d = make_int2(info.z, info.w);
            } else if (rank != maxr) {
                d = make_int2(c.x + c.y * W + c.z * H + c.w, info.x);
            }
        }
        desc[lin] = d;
    }
    __syncthreads();

    // ---- phase B: stream feats, accumulate T, fire atomics
    float4 tsum = make_float4(0.f, 0.f, 0.f, 0.f);
#pragma unroll
    for (int it = 0; it < KB; it++) {
        int r = it * 16 + ty;
        int row = base + r;
        if (row < N) {
            float4 v = __ldcs(&feats4[(long)row * C4 + tx]);
            tsum.x += v.x; tsum.y += v.y; tsum.z += v.z; tsum.w += v.w;
            int2 d = desc[r];
            if (d.x >= 0) {
                float L = (float)d.y;
                atomicAdd(&out4[(long)d.x * C4 + tx],
                          make_float4(L * v.x, L * v.y, L * v.z, L * v.w));
            }
        }
    }

    smr[ty][tx] = tsum;
    __syncthreads();
    if (ty == 0) {
        float4 a = smr[0][tx];
#pragma unroll
        for (int r = 1; r < 16; r++) {
            float4 b = smr[r][tx];
            a.x += b.x; a.y += b.y; a.z += b.z; a.w += b.w;
        }
        atomicAdd((float4*)&g_T[4 * tx], a);
    }
}

// ---------------------------------------------------------------- last interval + scalar state reset
__global__ void k_last(float* __restrict__ out, int C,
                       const int* __restrict__ Bp, const int* __restrict__ Dp,
                       const int* __restrict__ Hp, const int* __restrict__ Wp) {
    int m = g_maxrank;
    int L = g_info[m].x;
    int B = *Bp, D = *Dp, H = *Hp, W = *Wp;
    int s2 = B, s1 = D * B, s0 = W * s1;
    int c0 = m / s0; int r = m - c0 * s0;
    int c1 = r / s1; r -= c1 * s1;
    int c2 = r / s2; int c3 = r - c2 * s2;
    int g = c0 + c1 * W + c2 * H + c3;
    for (int c = threadIdx.x; c < C; c += blockDim.x) {
        atomicAdd(&out[(long)g * C + c], (float)L * g_T[c]);
    }
    __syncthreads();
    // restore zero-state for next replay
    for (int c = threadIdx.x; c < 256; c += blockDim.x) g_T[c] = 0.0f;
    if (threadIdx.x == 0) { g_wcount = 0; g_maxrank = 0; }
}

// ---------------------------------------------------------------- launch
extern "C" void kernel_launch(void* const* d_in, const int* in_sizes, int n_in,
                              void* d_out, int out_size) {
    const float* feats  = (const float*)d_in[0];
    const int*   coords = (const int*)d_in[1];
    const int*   Bp     = (const int*)d_in[2];
    const int*   Dp     = (const int*)d_in[3];
    const int*   Hp     = (const int*)d_in[4];
    const int*   Wp     = (const int*)d_in[5];

    int N  = in_sizes[1] / 4;
    int C  = in_sizes[0] / N;
    int C4 = C / 4;                 // C=80 -> 20

    int maxItems = N < MAX_RANKS ? N : MAX_RANKS;
    long n4 = (long)out_size / 4;

    k_hist<<<(N + 255) / 256, 256>>>((const int4*)coords, N, Bp, Dp, Wp);
    k_prep<<<(maxItems + 255) / 256, 256>>>(N, Bp, Dp, Hp, Wp,
                                            (float4*)d_out, n4, C4);

    dim3 b2(C4, 16);
    k_main<<<(N + ROWS - 1) / ROWS, b2>>>(
        (const float4*)feats, (const int4*)coords, (float4*)d_out, N, C4, n4,
        Bp, Dp, Hp, Wp);

    k_last<<<1, 256>>>((float*)d_out, C, Bp, Dp, Hp, Wp);
}

// round 11
// speedup vs baseline: 1.0727x; 1.0727x over previous
#include <cuda_runtime.h>
#include <cuda_bf16.h>

#define MAX_RANKS (1 << 20)

// Zero is the valid initial state for ALL of these (module load zeroes .bss;
// k_main resets g_meta, k_last resets scalars, so graph replays are clean).
__device__ int2  g_meta[MAX_RANKS];     // .x = count, .y = max(N - i) (first = N - y)
__device__ int4  g_info[MAX_RANKS];     // {count, first, g_pred(-1 none), L_pred}
__device__ int   g_worklist[MAX_RANKS];
__device__ int   g_wcount;
__device__ int   g_maxrank;
__device__ float g_T[256];

// hot region = output rows reachable by geom = c0 + c1*W + c2*H + c3
__device__ __forceinline__ long hot_bound(int B, int D, int H, int W, int C4, long n4) {
    long gmax = (long)(W - 1) + (long)(H - 1) * W + (long)(D - 1) * H + (B - 1);
    long hot = (gmax + 1) * C4;
    return hot < n4 ? hot : n4;
}

// ---------------------------------------------------------------- pass A: histogram + cold-zero (first 2/3)
__global__ void k_hist(const int4* __restrict__ coords, int N,
                       const int* __restrict__ Bp, const int* __restrict__ Dp,
                       const int* __restrict__ Hp, const int* __restrict__ Wp,
                       float4* __restrict__ out4z, long n4, int C4) {
    int i = blockIdx.x * blockDim.x + threadIdx.x;
    int B = *Bp, D = *Dp, H = *Hp, W = *Wp;

    // cold-zero slice [hot, split)
    long hot = hot_bound(B, D, H, W, C4, n4);
    long split = hot + ((n4 - hot) * 2) / 3;
    long zstride = (long)gridDim.x * blockDim.x;
    float4 zero = make_float4(0.f, 0.f, 0.f, 0.f);
    for (long z = hot + i; z < split; z += zstride)
        __stcs(&out4z[z], zero);

    int s2 = B, s1 = D * B, s0 = W * s1;
    int myrank = 0;
    if (i < N) {
        int4 c = __ldcs(&coords[i]);
        int rank = c.x * s0 + c.y * s1 + c.z * s2 + c.w;
        myrank = rank;
        int old = atomicAdd(&g_meta[rank].x, 1);
        if (old == 0) {
            int pos = atomicAdd(&g_wcount, 1);
            g_worklist[pos] = rank;
        }
        atomicMax(&g_meta[rank].y, N - i);    // first = N - max
    }
    __shared__ int sm[256];
    sm[threadIdx.x] = myrank;
    __syncthreads();
    for (int off = 128; off > 0; off >>= 1) {
        if (threadIdx.x < off) sm[threadIdx.x] = max(sm[threadIdx.x], sm[threadIdx.x + off]);
        __syncthreads();
    }
    if (threadIdx.x == 0) atomicMax(&g_maxrank, sm[0]);
}

// ---------------------------------------------------------------- prep: per-rank fused info + cold tail + HOT zero
__global__ void k_prep(int N,
                       const int* __restrict__ Bp, const int* __restrict__ Dp,
                       const int* __restrict__ Hp, const int* __restrict__ Wp,
                       float4* __restrict__ out4z, long n4, int C4) {
    int w = blockIdx.x * blockDim.x + threadIdx.x;
    int B = *Bp, D = *Dp, H = *Hp, W = *Wp;

    long hot = hot_bound(B, D, H, W, C4, n4);
    long split = hot + ((n4 - hot) * 2) / 3;
    long zstride = (long)gridDim.x * blockDim.x;
    float4 zero = make_float4(0.f, 0.f, 0.f, 0.f);
    // cold tail (streaming stores: don't pollute L2)
    for (long z = split + w; z < n4; z += zstride)
        __stcs(&out4z[z], zero);
    // hot region LAST with normal stores -> stays L2-resident into k_main
    for (long z = w; z < hot; z += zstride)
        out4z[z] = zero;

    if (w >= g_wcount) return;
    int j = g_worklist[w];

    int s2 = B, s1 = D * B, s0 = W * s1;
    int2 mj = g_meta[j];
    int first = N - mj.y;

    int p = j - 1;
    int Lp = 0;
    while (p >= 0) {
        Lp = g_meta[p].x;
        if (Lp != 0) break;
        p--;
    }
    int gp = -1;
    if (p >= 0) {
        int d0 = p / s0; int rr = p - d0 * s0;
        int d1 = rr / s1; rr -= d1 * s1;
        int d2 = rr / s2; int d3 = rr - d2 * s2;
        gp = d0 + d1 * W + d2 * H + d3;
    }
    g_info[j] = make_int4(mj.x, first, gp, Lp);
}

// ---------------------------------------------------------------- main streaming pass (R9 shape + tiny meta-reset side job)
#define KB 16
#define ROWS (16 * KB)
#define TPB 320
__global__ void k_main(const float4* __restrict__ feats4, const int4* __restrict__ coords,
                       float4* __restrict__ out4, int N, int C4,
                       const int* __restrict__ Bp, const int* __restrict__ Dp,
                       const int* __restrict__ Hp, const int* __restrict__ Wp) {
    __shared__ int2   desc[ROWS];        // {target geom or -1, L}
    __shared__ float4 smr[16][64];

    int tx = threadIdx.x;          // channel chunk (0..C4-1)
    int ty = threadIdx.y;          // row-in-tile (0..15)
    int lin = ty * C4 + tx;
    int base = blockIdx.x * ROWS;
    int maxr = g_maxrank;

    // side job: restore g_meta zeros for next replay (8MB, not read here)
    {
        long gtid = (long)blockIdx.x * TPB + lin;
        long gstride = (long)gridDim.x * TPB;
        for (long i = gtid; i < MAX_RANKS; i += gstride)
            g_meta[i] = make_int2(0, 0);
    }

    // ---- phase A: per-row metadata -> smem
    if (lin < ROWS) {
        int row = base + lin;
        int2 d = make_int2(-1, 0);
        if (row < N) {
            int B = *Bp, D = *Dp, H = *Hp, W = *Wp;
            int s2 = B, s1 = D * B, s0 = W * s1;
            int4 c = __ldcs(&coords[row]);
            int rank = c.x * s0 + c.y * s1 + c.z * s2 + c.w;
            int4 info = g_info[rank];
            if (row == info.y) {                 // first point of its rank
                if (info.z >= 0) d = make_int2(info.z, info.w);
            } else if (rank != maxr) {
                d = make_int2(c.x + c.y * W + c.z * H + c.w, info.x);
            }
        }
        desc[lin] = d;
    }
    __syncthreads();

    // ---- phase B: stream feats, accumulate T, fire atomics
    float4 tsum = make_float4(0.f, 0.f, 0.f, 0.f);
#pragma unroll
    for (int it = 0; it < KB; it++) {
        int r = it * 16 + ty;
        int row = base + r;
        if (row < N) {
            float4 v = __ldcs(&feats4[(long)row * C4 + tx]);
            tsum.x += v.x; tsum.y += v.y; tsum.z += v.z; tsum.w += v.w;
            int2 d = desc[r];
            if (d.x >= 0) {
                float L = (float)d.y;
                atomicAdd(&out4[(long)d.x * C4 + tx],
                          make_float4(L * v.x, L * v.y, L * v.z, L * v.w));
            }
        }
    }

    smr[ty][tx] = tsum;
    __syncthreads();
    if (ty == 0) {
        float4 a = smr[0][tx];
#pragma unroll
        for (int r = 1; r < 16; r++) {
            float4 b = smr[r][tx];
            a.x += b.x; a.y += b.y; a.z += b.z; a.w += b.w;
        }
        atomicAdd((float4*)&g_T[4 * tx], a);
    }
}

// ---------------------------------------------------------------- last interval + scalar state reset
__global__ void k_last(float* __restrict__ out, int C,
                       const int* __restrict__ Bp, const int* __restrict__ Dp,
                       const int* __restrict__ Hp, const int* __restrict__ Wp) {
    int m = g_maxrank;
    int L = g_info[m].x;
    int B = *Bp, D = *Dp, H = *Hp, W = *Wp;
    int s2 = B, s1 = D * B, s0 = W * s1;
    int c0 = m / s0; int r = m - c0 * s0;
    int c1 = r / s1; r -= c1 * s1;
    int c2 = r / s2; int c3 = r - c2 * s2;
    int g = c0 + c1 * W + c2 * H + c3;
    for (int c = threadIdx.x; c < C; c += blockDim.x)
        atomicAdd(&out[(long)g * C + c], (float)L * g_T[c]);
    __syncthreads();
    // restore zero-state for next replay
    for (int c = threadIdx.x; c < 256; c += blockDim.x) g_T[c] = 0.0f;
    if (threadIdx.x == 0) { g_wcount = 0; g_maxrank = 0; }
}

// ---------------------------------------------------------------- launch
extern "C" void kernel_launch(void* const* d_in, const int* in_sizes, int n_in,
                              void* d_out, int out_size) {
    const float* feats  = (const float*)d_in[0];
    const int*   coords = (const int*)d_in[1];
    const int*   Bp     = (const int*)d_in[2];
    const int*   Dp     = (const int*)d_in[3];
    const int*   Hp     = (const int*)d_in[4];
    const int*   Wp     = (const int*)d_in[5];

    int N  = in_sizes[1] / 4;
    int C  = in_sizes[0] / N;
    int C4 = C / 4;                 // C=80 -> 20

    int maxItems = N < MAX_RANKS ? N : MAX_RANKS;
    long n4 = (long)out_size / 4;

    k_hist<<<(N + 255) / 256, 256>>>((const int4*)coords, N, Bp, Dp, Hp, Wp,
                                     (float4*)d_out, n4, C4);
    k_prep<<<(maxItems + 255) / 256, 256>>>(N, Bp, Dp, Hp, Wp,
                                            (float4*)d_out, n4, C4);

    dim3 b2(C4, 16);
    k_main<<<(N + ROWS - 1) / ROWS, b2>>>(
        (const float4*)feats, (const int4*)coords, (float4*)d_out, N, C4,
        Bp, Dp, Hp, Wp);

    k_last<<<1, 256>>>((float*)d_out, C, Bp, Dp, Hp, Wp);
}

// round 12
// speedup vs baseline: 1.1679x; 1.0888x over previous
#include <cuda_runtime.h>
#include <cuda_bf16.h>

#define MAX_RANKS (1 << 20)

// Zero is the valid initial state (module load zeroes .bss; k_main restores
// zeros at the end of every call, so graph replays are self-consistent).
__device__ int2 g_meta[MAX_RANKS];   // .x = count, .y = max(N - i)  (first = N - y)
__device__ int4 g_info[MAX_RANKS];   // {count, first, g_pred(-1 none), L_pred}
__device__ int  g_maxrank;           // reset by k_main side job
__device__ int4 g_lastinfo;          // {maxrank, g_last, L_last, 0} written by k_prep each call

// hot region = output rows reachable by geom = c0 + c1*W + c2*H + c3
__device__ __forceinline__ long hot_bound(int B, int D, int H, int W, int C4, long n4) {
    long gmax = (long)(W - 1) + (long)(H - 1) * W + (long)(D - 1) * H + (B - 1);
    long hot = (gmax + 1) * C4;
    return hot < n4 ? hot : n4;
}

// ---------------------------------------------------------------- cold-zero (separate stream, overlaps hist+prep)
__global__ void k_zero(const int* __restrict__ Bp, const int* __restrict__ Dp,
                       const int* __restrict__ Hp, const int* __restrict__ Wp,
                       float4* __restrict__ out4z, long n4, int C4) {
    int B = *Bp, D = *Dp, H = *Hp, W = *Wp;
    long hot = hot_bound(B, D, H, W, C4, n4);
    long t = (long)blockIdx.x * blockDim.x + threadIdx.x;
    long stride = (long)gridDim.x * blockDim.x;
    float4 zero = make_float4(0.f, 0.f, 0.f, 0.f);
    for (long z = hot + t; z < n4; z += stride)
        __stcs(&out4z[z], zero);
}

// ---------------------------------------------------------------- pass A: pure histogram
__global__ void k_hist(const int4* __restrict__ coords, int N,
                       const int* __restrict__ Bp, const int* __restrict__ Dp,
                       const int* __restrict__ Wp) {
    int i = blockIdx.x * blockDim.x + threadIdx.x;
    int B = *Bp, D = *Dp, W = *Wp;
    int s2 = B, s1 = D * B, s0 = W * s1;
    int myrank = 0;
    if (i < N) {
        int4 c = __ldcs(&coords[i]);
        int rank = c.x * s0 + c.y * s1 + c.z * s2 + c.w;
        myrank = rank;
        atomicAdd(&g_meta[rank].x, 1);
        atomicMax(&g_meta[rank].y, N - i);    // first = N - max
    }
    __shared__ int sm[256];
    sm[threadIdx.x] = myrank;
    __syncthreads();
    for (int off = 128; off > 0; off >>= 1) {
        if (threadIdx.x < off) sm[threadIdx.x] = max(sm[threadIdx.x], sm[threadIdx.x + off]);
        __syncthreads();
    }
    if (threadIdx.x == 0) atomicMax(&g_maxrank, sm[0]);
}

// ---------------------------------------------------------------- prep: one thread per rank + HOT zero (L2-resident into k_main)
__global__ void k_prep(int N,
                       const int* __restrict__ Bp, const int* __restrict__ Dp,
                       const int* __restrict__ Hp, const int* __restrict__ Wp,
                       float4* __restrict__ out4z, long n4, int C4) {
    int j = blockIdx.x * blockDim.x + threadIdx.x;
    int B = *Bp, D = *Dp, H = *Hp, W = *Wp;

    // hot-zero (normal stores -> stays L2-resident into k_main)
    long hot = hot_bound(B, D, H, W, C4, n4);
    long zstride = (long)gridDim.x * blockDim.x;
    for (long z = j; z < hot; z += zstride)
        out4z[z] = make_float4(0.f, 0.f, 0.f, 0.f);

    if (j >= MAX_RANKS) return;
    int2 mj = g_meta[j];
    if (mj.x == 0) return;                 // unoccupied rank

    int s2 = B, s1 = D * B, s0 = W * s1;
    int first = N - mj.y;

    int p = j - 1;
    int Lp = 0;
    while (p >= 0) {
        Lp = g_meta[p].x;
        if (Lp != 0) break;
        p--;
    }
    int gp = -1;
    if (p >= 0) {
        int d0 = p / s0; int rr = p - d0 * s0;
        int d1 = rr / s1; rr -= d1 * s1;
        int d2 = rr / s2; int d3 = rr - d2 * s2;
        gp = d0 + d1 * W + d2 * H + d3;
    }
    g_info[j] = make_int4(mj.x, first, gp, Lp);

    if (j == g_maxrank) {                  // publish last-interval target
        int c0 = j / s0; int rr = j - c0 * s0;
        int c1 = rr / s1; rr -= c1 * s1;
        int c2 = rr / s2; int c3 = rr - c2 * s2;
        int gj = c0 + c1 * W + c2 * H + c3;
        g_lastinfo = make_int4(j, gj, mj.x, 0);
    }
}

// ---------------------------------------------------------------- main streaming pass (fused last-interval, per-block partial)
#define KB 16
#define ROWS (16 * KB)
#define TPB 320
__global__ void k_main(const float4* __restrict__ feats4, const int4* __restrict__ coords,
                       float4* __restrict__ out4, int N, int C4,
                       const int* __restrict__ Bp, const int* __restrict__ Dp,
                       const int* __restrict__ Hp, const int* __restrict__ Wp) {
    __shared__ int2   desc[ROWS];        // {target geom or -1, L}
    __shared__ float4 smr[16][64];

    int tx = threadIdx.x;          // channel chunk (0..C4-1)
    int ty = threadIdx.y;          // row-in-tile (0..15)
    int lin = ty * C4 + tx;
    int base = blockIdx.x * ROWS;

    int4 li = g_lastinfo;          // {maxrank, g_last, L_last, 0}
    int maxr = li.x;

    // ---- phase A: per-row metadata -> smem
    if (lin < ROWS) {
        int row = base + lin;
        int2 d = make_int2(-1, 0);
        if (row < N) {
            int B = *Bp, D = *Dp, H = *Hp, W = *Wp;
            int s2 = B, s1 = D * B, s0 = W * s1;
            int4 c = __ldcs(&coords[row]);
            int rank = c.x * s0 + c.y * s1 + c.z * s2 + c.w;
            int4 info = g_info[rank];
            if (row == info.y) {                 // first point of its rank
                if (info.z >= 0) d = make_int2(info.z, info.w);
            } else if (rank != maxr) {
                d = make_int2(c.x + c.y * W + c.z * H + c.w, info.x);
            }
        }
        desc[lin] = d;
    }
    __syncthreads();

    // ---- phase B: stream feats, accumulate T-partial, fire atomics
    float4 tsum = make_float4(0.f, 0.f, 0.f, 0.f);
#pragma unroll
    for (int it = 0; it < KB; it++) {
        int r = it * 16 + ty;
        int row = base + r;
        if (row < N) {
            float4 v = __ldcs(&feats4[(long)row * C4 + tx]);
            tsum.x += v.x; tsum.y += v.y; tsum.z += v.z; tsum.w += v.w;
            int2 d = desc[r];
            if (d.x >= 0) {
                float L = (float)d.y;
                atomicAdd(&out4[(long)d.x * C4 + tx],
                          make_float4(L * v.x, L * v.y, L * v.z, L * v.w));
            }
        }
    }

    // ---- fused last-interval: out[g_last] += L_last * (block-partial sum)
    smr[ty][tx] = tsum;
    __syncthreads();
    if (ty == 0) {
        float4 a = smr[0][tx];
#pragma unroll
        for (int r = 1; r < 16; r++) {
            float4 b = smr[r][tx];
            a.x += b.x; a.y += b.y; a.z += b.z; a.w += b.w;
        }
        float L = (float)li.z;
        atomicAdd(&out4[(long)li.y * C4 + tx],
                  make_float4(L * a.x, L * a.y, L * a.z, L * a.w));
    }

    // ---- side job: restore zero-state for next replay (nothing reads these here)
    long gtid = (long)blockIdx.x * TPB + lin;
    long gstride = (long)gridDim.x * TPB;
    for (long i = gtid; i < MAX_RANKS; i += gstride)
        g_meta[i] = make_int2(0, 0);
    if (gtid == 0) g_maxrank = 0;
}

// ---------------------------------------------------------------- launch
extern "C" void kernel_launch(void* const* d_in, const int* in_sizes, int n_in,
                              void* d_out, int out_size) {
    static cudaStream_t s1 = nullptr;
    static cudaEvent_t  evF = nullptr, evJ = nullptr;
    if (s1 == nullptr) {
        cudaStreamCreateWithFlags(&s1, cudaStreamNonBlocking);
        cudaEventCreateWithFlags(&evF, cudaEventDisableTiming);
        cudaEventCreateWithFlags(&evJ, cudaEventDisableTiming);
    }

    const float* feats  = (const float*)d_in[0];
    const int*   coords = (const int*)d_in[1];
    const int*   Bp     = (const int*)d_in[2];
    const int*   Dp     = (const int*)d_in[3];
    const int*   Hp     = (const int*)d_in[4];
    const int*   Wp     = (const int*)d_in[5];

    int N  = in_sizes[1] / 4;
    int C  = in_sizes[0] / N;
    int C4 = C / 4;                 // C=80 -> 20
    long n4 = (long)out_size / 4;

    // fork: cold-zero on s1, concurrent with hist+prep on the main stream
    cudaEventRecord(evF, 0);
    cudaStreamWaitEvent(s1, evF, 0);
    k_zero<<<4096, 256, 0, s1>>>(Bp, Dp, Hp, Wp, (float4*)d_out, n4, C4);
    cudaEventRecord(evJ, s1);

    k_hist<<<(N + 255) / 256, 256>>>((const int4*)coords, N, Bp, Dp, Wp);
    k_prep<<<MAX_RANKS / 256, 256>>>(N, Bp, Dp, Hp, Wp, (float4*)d_out, n4, C4);

    // join: k_main needs both the prep tables and the cold-zero done
    cudaStreamWaitEvent(0, evJ, 0);

    dim3 b2(C4, 16);
    k_main<<<(N + ROWS - 1) / ROWS, b2>>>(
        (const float4*)feats, (const int4*)coords, (float4*)d_out, N, C4,
        Bp, Dp, Hp, Wp);
}

// round 13
// speedup vs baseline: 1.2085x; 1.0347x over previous
#include <cuda_runtime.h>
#include <cuda_bf16.h>

#define MAX_RANKS (1 << 20)

// Zero is the valid initial state (module load zeroes .bss; k_meta_reset
// restores zeros each call on the side stream, joined before graph end).
__device__ int2 g_meta[MAX_RANKS];   // .x = count, .y = max(N - i)  (first = N - y)
__device__ int4 g_info[MAX_RANKS];   // {count, first, g_pred(-1 none), L_pred}
__device__ int  g_maxrank;
__device__ int4 g_lastinfo;          // {maxrank, g_last, L_last, 0} written by k_prep

// hot region = output rows reachable by geom = c0 + c1*W + c2*H + c3
__device__ __forceinline__ long hot_bound(int B, int D, int H, int W, int C4, long n4) {
    long gmax = (long)(W - 1) + (long)(H - 1) * W + (long)(D - 1) * H + (B - 1);
    long hot = (gmax + 1) * C4;
    return hot < n4 ? hot : n4;
}

// ---------------------------------------------------------------- cold-zero (side stream, overlaps hist+prep)
__global__ void k_zero(const int* __restrict__ Bp, const int* __restrict__ Dp,
                       const int* __restrict__ Hp, const int* __restrict__ Wp,
                       float4* __restrict__ out4z, long n4, int C4) {
    int B = *Bp, D = *Dp, H = *Hp, W = *Wp;
    long hot = hot_bound(B, D, H, W, C4, n4);
    long t = (long)blockIdx.x * blockDim.x + threadIdx.x;
    long stride = (long)gridDim.x * blockDim.x;
    float4 zero = make_float4(0.f, 0.f, 0.f, 0.f);
    for (long z = hot + t; z < n4; z += stride)
        __stcs(&out4z[z], zero);
}

// ---------------------------------------------------------------- meta reset (side stream, overlaps k_main)
__global__ void k_meta_reset() {
    long t = (long)blockIdx.x * blockDim.x + threadIdx.x;
    long stride = (long)gridDim.x * blockDim.x;
    for (long i = t; i < MAX_RANKS; i += stride)
        g_meta[i] = make_int2(0, 0);
    if (t == 0) g_maxrank = 0;
}

// ---------------------------------------------------------------- pass A: pure histogram
__global__ void k_hist(const int4* __restrict__ coords, int N,
                       const int* __restrict__ Bp, const int* __restrict__ Dp,
                       const int* __restrict__ Wp) {
    int i = blockIdx.x * blockDim.x + threadIdx.x;
    int B = *Bp, D = *Dp, W = *Wp;
    int s2 = B, s1 = D * B, s0 = W * s1;
    int myrank = 0;
    if (i < N) {
        int4 c = __ldcs(&coords[i]);
        int rank = c.x * s0 + c.y * s1 + c.z * s2 + c.w;
        myrank = rank;
        atomicAdd(&g_meta[rank].x, 1);
        atomicMax(&g_meta[rank].y, N - i);    // first = N - max
    }
    __shared__ int sm[256];
    sm[threadIdx.x] = myrank;
    __syncthreads();
    for (int off = 128; off > 0; off >>= 1) {
        if (threadIdx.x < off) sm[threadIdx.x] = max(sm[threadIdx.x], sm[threadIdx.x + off]);
        __syncthreads();
    }
    if (threadIdx.x == 0) atomicMax(&g_maxrank, sm[0]);
}

// ---------------------------------------------------------------- prep: one thread per rank + HOT zero (L2-resident into k_main)
__global__ void k_prep(int N,
                       const int* __restrict__ Bp, const int* __restrict__ Dp,
                       const int* __restrict__ Hp, const int* __restrict__ Wp,
                       float4* __restrict__ out4z, long n4, int C4) {
    int j = blockIdx.x * blockDim.x + threadIdx.x;
    int B = *Bp, D = *Dp, H = *Hp, W = *Wp;

    // hot-zero (normal stores -> stays L2-resident into k_main)
    long hot = hot_bound(B, D, H, W, C4, n4);
    long zstride = (long)gridDim.x * blockDim.x;
    for (long z = j; z < hot; z += zstride)
        out4z[z] = make_float4(0.f, 0.f, 0.f, 0.f);

    if (j >= MAX_RANKS) return;
    int2 mj = g_meta[j];
    if (mj.x == 0) return;                 // unoccupied rank

    int s2 = B, s1 = D * B, s0 = W * s1;
    int first = N - mj.y;

    int p = j - 1;
    int Lp = 0;
    while (p >= 0) {
        Lp = g_meta[p].x;
        if (Lp != 0) break;
        p--;
    }
    int gp = -1;
    if (p >= 0) {
        int d0 = p / s0; int rr = p - d0 * s0;
        int d1 = rr / s1; rr -= d1 * s1;
        int d2 = rr / s2; int d3 = rr - d2 * s2;
        gp = d0 + d1 * W + d2 * H + d3;
    }
    g_info[j] = make_int4(mj.x, first, gp, Lp);

    if (j == g_maxrank) {                  // publish last-interval target
        int c0 = j / s0; int rr = j - c0 * s0;
        int c1 = rr / s1; rr -= c1 * s1;
        int c2 = rr / s2; int c3 = rr - c2 * s2;
        int gj = c0 + c1 * W + c2 * H + c3;
        g_lastinfo = make_int4(j, gj, mj.x, 0);
    }
}

// ---------------------------------------------------------------- main streaming pass (fused last-interval per-block partial)
#define KB 16
#define ROWS (16 * KB)
__global__ void k_main(const float4* __restrict__ feats4, const int4* __restrict__ coords,
                       float4* __restrict__ out4, int N, int C4,
                       const int* __restrict__ Bp, const int* __restrict__ Dp,
                       const int* __restrict__ Hp, const int* __restrict__ Wp) {
    __shared__ int2   desc[ROWS];        // {target geom or -1, L}
    __shared__ float4 smr[16][64];

    int tx = threadIdx.x;          // channel chunk (0..C4-1)
    int ty = threadIdx.y;          // row-in-tile (0..15)
    int lin = ty * C4 + tx;
    int base = blockIdx.x * ROWS;

    int4 li = g_lastinfo;          // {maxrank, g_last, L_last, 0}
    int maxr = li.x;

    // ---- phase A: per-row metadata -> smem
    if (lin < ROWS) {
        int row = base + lin;
        int2 d = make_int2(-1, 0);
        if (row < N) {
            int B = *Bp, D = *Dp, H = *Hp, W = *Wp;
            int s2 = B, s1 = D * B, s0 = W * s1;
            int4 c = __ldcs(&coords[row]);
            int rank = c.x * s0 + c.y * s1 + c.z * s2 + c.w;
            int4 info = g_info[rank];
            if (row == info.y) {                 // first point of its rank
                if (info.z >= 0) d = make_int2(info.z, info.w);
            } else if (rank != maxr) {
                d = make_int2(c.x + c.y * W + c.z * H + c.w, info.x);
            }
        }
        desc[lin] = d;
    }
    __syncthreads();

    // ---- phase B: stream feats, accumulate T-partial, fire atomics
    float4 tsum = make_float4(0.f, 0.f, 0.f, 0.f);
#pragma unroll
    for (int it = 0; it < KB; it++) {
        int r = it * 16 + ty;
        int row = base + r;
        if (row < N) {
            float4 v = __ldcs(&feats4[(long)row * C4 + tx]);
            tsum.x += v.x; tsum.y += v.y; tsum.z += v.z; tsum.w += v.w;
            int2 d = desc[r];
            if (d.x >= 0) {
                float L = (float)d.y;
                atomicAdd(&out4[(long)d.x * C4 + tx],
                          make_float4(L * v.x, L * v.y, L * v.z, L * v.w));
            }
        }
    }

    // ---- fused last-interval: out[g_last] += L_last * (block-partial sum)
    smr[ty][tx] = tsum;
    __syncthreads();
    if (ty == 0) {
        float4 a = smr[0][tx];
#pragma unroll
        for (int r = 1; r < 16; r++) {
            float4 b = smr[r][tx];
            a.x += b.x; a.y += b.y; a.z += b.z; a.w += b.w;
        }
        float L = (float)li.z;
        atomicAdd(&out4[(long)li.y * C4 + tx],
                  make_float4(L * a.x, L * a.y, L * a.z, L * a.w));
    }
}

// ---------------------------------------------------------------- launch
extern "C" void kernel_launch(void* const* d_in, const int* in_sizes, int n_in,
                              void* d_out, int out_size) {
    static cudaStream_t s1 = nullptr;
    static cudaEvent_t  evF = nullptr, evZ = nullptr, evP = nullptr, evM = nullptr;
    if (s1 == nullptr) {
        cudaStreamCreateWithFlags(&s1, cudaStreamNonBlocking);
        cudaEventCreateWithFlags(&evF, cudaEventDisableTiming);
        cudaEventCreateWithFlags(&evZ, cudaEventDisableTiming);
        cudaEventCreateWithFlags(&evP, cudaEventDisableTiming);
        cudaEventCreateWithFlags(&evM, cudaEventDisableTiming);
    }

    const float* feats  = (const float*)d_in[0];
    const int*   coords = (const int*)d_in[1];
    const int*   Bp     = (const int*)d_in[2];
    const int*   Dp     = (const int*)d_in[3];
    const int*   Hp     = (const int*)d_in[4];
    const int*   Wp     = (const int*)d_in[5];

    int N  = in_sizes[1] / 4;
    int C  = in_sizes[0] / N;
    int C4 = C / 4;                 // C=80 -> 20
    long n4 = (long)out_size / 4;

    // fork: cold-zero on s1, concurrent with hist+prep on the main stream
    cudaEventRecord(evF, 0);
    cudaStreamWaitEvent(s1, evF, 0);
    k_zero<<<4096, 256, 0, s1>>>(Bp, Dp, Hp, Wp, (float4*)d_out, n4, C4);

    k_hist<<<(N + 255) / 256, 256>>>((const int4*)coords, N, Bp, Dp, Wp);
    k_prep<<<MAX_RANKS / 256, 256>>>(N, Bp, Dp, Hp, Wp, (float4*)d_out, n4, C4);
    cudaEventRecord(evP, 0);                 // prep done: g_meta no longer needed

    // s1: after its zero AND prep, reset g_meta concurrently with k_main
    cudaStreamWaitEvent(s1, evP, 0);
    cudaEventRecord(evZ, s1);                // cold-zero (and queue position) marker
    k_meta_reset<<<512, 256, 0, s1>>>();
    cudaEventRecord(evM, s1);

    // main: k_main needs prep tables + cold-zero done
    cudaStreamWaitEvent(0, evZ, 0);
    dim3 b2(C4, 16);
    k_main<<<(N + ROWS - 1) / ROWS, b2>>>(
        (const float4*)feats, (const int4*)coords, (float4*)d_out, N, C4,
        Bp, Dp, Hp, Wp);

    // join meta reset before graph end (clean state for next replay)
    cudaStreamWaitEvent(0, evM, 0);
}

// round 14
// speedup vs baseline: 1.2169x; 1.0069x over previous
#include <cuda_runtime.h>
#include <cuda_bf16.h>

#define MAX_RANKS (1 << 20)

// Zero is the valid initial state (module load zeroes .bss; k_meta_reset
// restores zeros each call on the side stream, joined before graph end).
__device__ int2 g_meta[MAX_RANKS];   // .x = count, .y = max(N - i)  (first = N - y)
__device__ int4 g_info[MAX_RANKS];   // {count, first, g_pred(-1 none), L_pred}
__device__ int  g_maxrank;
__device__ int4 g_lastinfo;          // {maxrank, g_last, L_last, 0} written by k_prep

// hot region = output rows reachable by geom = c0 + c1*W + c2*H + c3
__device__ __forceinline__ long hot_bound(int B, int D, int H, int W, int C4, long n4) {
    long gmax = (long)(W - 1) + (long)(H - 1) * W + (long)(D - 1) * H + (B - 1);
    long hot = (gmax + 1) * C4;
    return hot < n4 ? hot : n4;
}

// ---------------------------------------------------------------- cold-zero (side stream; streaming stores)
__global__ void k_zero_cold(const int* __restrict__ Bp, const int* __restrict__ Dp,
                            const int* __restrict__ Hp, const int* __restrict__ Wp,
                            float4* __restrict__ out4z, long n4, int C4) {
    int B = *Bp, D = *Dp, H = *Hp, W = *Wp;
    long hot = hot_bound(B, D, H, W, C4, n4);
    long t = (long)blockIdx.x * blockDim.x + threadIdx.x;
    long stride = (long)gridDim.x * blockDim.x;
    float4 zero = make_float4(0.f, 0.f, 0.f, 0.f);
    for (long z = hot + t; z < n4; z += stride)
        __stcs(&out4z[z], zero);
}

// ---------------------------------------------------------------- hot-zero (side stream; normal stores -> L2-resident)
__global__ void k_zero_hot(const int* __restrict__ Bp, const int* __restrict__ Dp,
                           const int* __restrict__ Hp, const int* __restrict__ Wp,
                           float4* __restrict__ out4z, long n4, int C4) {
    int B = *Bp, D = *Dp, H = *Hp, W = *Wp;
    long hot = hot_bound(B, D, H, W, C4, n4);
    long t = (long)blockIdx.x * blockDim.x + threadIdx.x;
    long stride = (long)gridDim.x * blockDim.x;
    float4 zero = make_float4(0.f, 0.f, 0.f, 0.f);
    for (long z = t; z < hot; z += stride)
        out4z[z] = zero;
}

// ---------------------------------------------------------------- meta reset (side stream, overlaps k_main)
__global__ void k_meta_reset() {
    long t = (long)blockIdx.x * blockDim.x + threadIdx.x;
    long stride = (long)gridDim.x * blockDim.x;
    for (long i = t; i < MAX_RANKS; i += stride)
        g_meta[i] = make_int2(0, 0);
    if (t == 0) g_maxrank = 0;
}

// ---------------------------------------------------------------- pass A: pure histogram
__global__ void k_hist(const int4* __restrict__ coords, int N,
                       const int* __restrict__ Bp, const int* __restrict__ Dp,
                       const int* __restrict__ Wp) {
    int i = blockIdx.x * blockDim.x + threadIdx.x;
    int B = *Bp, D = *Dp, W = *Wp;
    int s2 = B, s1 = D * B, s0 = W * s1;
    int myrank = 0;
    if (i < N) {
        int4 c = __ldcs(&coords[i]);
        int rank = c.x * s0 + c.y * s1 + c.z * s2 + c.w;
        myrank = rank;
        atomicAdd(&g_meta[rank].x, 1);
        atomicMax(&g_meta[rank].y, N - i);    // first = N - max
    }
    __shared__ int sm[256];
    sm[threadIdx.x] = myrank;
    __syncthreads();
    for (int off = 128; off > 0; off >>= 1) {
        if (threadIdx.x < off) sm[threadIdx.x] = max(sm[threadIdx.x], sm[threadIdx.x + off]);
        __syncthreads();
    }
    if (threadIdx.x == 0) atomicMax(&g_maxrank, sm[0]);
}

// ---------------------------------------------------------------- prep: one thread per rank (pure table work)
__global__ void k_prep(int N,
                       const int* __restrict__ Bp, const int* __restrict__ Dp,
                       const int* __restrict__ Hp, const int* __restrict__ Wp) {
    int j = blockIdx.x * blockDim.x + threadIdx.x;
    if (j >= MAX_RANKS) return;
    int2 mj = g_meta[j];
    if (mj.x == 0) return;                 // unoccupied rank

    int B = *Bp, D = *Dp, H = *Hp, W = *Wp;
    int s2 = B, s1 = D * B, s0 = W * s1;
    int first = N - mj.y;

    int p = j - 1;
    int Lp = 0;
    while (p >= 0) {
        Lp = g_meta[p].x;
        if (Lp != 0) break;
        p--;
    }
    int gp = -1;
    if (p >= 0) {
        int d0 = p / s0; int rr = p - d0 * s0;
        int d1 = rr / s1; rr -= d1 * s1;
        int d2 = rr / s2; int d3 = rr - d2 * s2;
        gp = d0 + d1 * W + d2 * H + d3;
    }
    g_info[j] = make_int4(mj.x, first, gp, Lp);

    if (j == g_maxrank) {                  // publish last-interval target
        int c0 = j / s0; int rr = j - c0 * s0;
        int c1 = rr / s1; rr -= c1 * s1;
        int c2 = rr / s2; int c3 = rr - c2 * s2;
        int gj = c0 + c1 * W + c2 * H + c3;
        g_lastinfo = make_int4(j, gj, mj.x, 0);
    }
}

// ---------------------------------------------------------------- main streaming pass (fused last-interval per-block partial)
#define KB 16
#define ROWS (16 * KB)
__global__ void k_main(const float4* __restrict__ feats4, const int4* __restrict__ coords,
                       float4* __restrict__ out4, int N, int C4,
                       const int* __restrict__ Bp, const int* __restrict__ Dp,
                       const int* __restrict__ Hp, const int* __restrict__ Wp) {
    __shared__ int2   desc[ROWS];        // {target geom or -1, L}
    __shared__ float4 smr[16][64];

    int tx = threadIdx.x;          // channel chunk (0..C4-1)
    int ty = threadIdx.y;          // row-in-tile (0..15)
    int lin = ty * C4 + tx;
    int base = blockIdx.x * ROWS;

    int4 li = g_lastinfo;          // {maxrank, g_last, L_last, 0}
    int maxr = li.x;

    // ---- phase A: per-row metadata -> smem
    if (lin < ROWS) {
        int row = base + lin;
        int2 d = make_int2(-1, 0);
        if (row < N) {
            int B = *Bp, D = *Dp, H = *Hp, W = *Wp;
            int s2 = B, s1 = D * B, s0 = W * s1;
            int4 c = __ldcs(&coords[row]);
            int rank = c.x * s0 + c.y * s1 + c.z * s2 + c.w;
            int4 info = g_info[rank];
            if (row == info.y) {                 // first point of its rank
                if (info.z >= 0) d = make_int2(info.z, info.w);
            } else if (rank != maxr) {
                d = make_int2(c.x + c.y * W + c.z * H + c.w, info.x);
            }
        }
        desc[lin] = d;
    }
    __syncthreads();

    // ---- phase B: stream feats, accumulate T-partial, fire atomics
    float4 tsum = make_float4(0.f, 0.f, 0.f, 0.f);
#pragma unroll
    for (int it = 0; it < KB; it++) {
        int r = it * 16 + ty;
        int row = base + r;
        if (row < N) {
            float4 v = __ldcs(&feats4[(long)row * C4 + tx]);
            tsum.x += v.x; tsum.y += v.y; tsum.z += v.z; tsum.w += v.w;
            int2 d = desc[r];
            if (d.x >= 0) {
                float L = (float)d.y;
                atomicAdd(&out4[(long)d.x * C4 + tx],
                          make_float4(L * v.x, L * v.y, L * v.z, L * v.w));
            }
        }
    }

    // ---- fused last-interval: out[g_last] += L_last * (block-partial sum)
    smr[ty][tx] = tsum;
    __syncthreads();
    if (ty == 0) {
        float4 a = smr[0][tx];
#pragma unroll
        for (int r = 1; r < 16; r++) {
            float4 b = smr[r][tx];
            a.x += b.x; a.y += b.y; a.z += b.z; a.w += b.w;
        }
        float L = (float)li.z;
        atomicAdd(&out4[(long)li.y * C4 + tx],
                  make_float4(L * a.x, L * a.y, L * a.z, L * a.w));
    }
}

// ---------------------------------------------------------------- launch
extern "C" void kernel_launch(void* const* d_in, const int* in_sizes, int n_in,
                              void* d_out, int out_size) {
    static cudaStream_t s1 = nullptr;
    static cudaEvent_t  evF = nullptr, evZ = nullptr, evP = nullptr, evM = nullptr;
    if (s1 == nullptr) {
        cudaStreamCreateWithFlags(&s1, cudaStreamNonBlocking);
        cudaEventCreateWithFlags(&evF, cudaEventDisableTiming);
        cudaEventCreateWithFlags(&evZ, cudaEventDisableTiming);
        cudaEventCreateWithFlags(&evP, cudaEventDisableTiming);
        cudaEventCreateWithFlags(&evM, cudaEventDisableTiming);
    }

    const float* feats  = (const float*)d_in[0];
    const int*   coords = (const int*)d_in[1];
    const int*   Bp     = (const int*)d_in[2];
    const int*   Dp     = (const int*)d_in[3];
    const int*   Hp     = (const int*)d_in[4];
    const int*   Wp     = (const int*)d_in[5];

    int N  = in_sizes[1] / 4;
    int C  = in_sizes[0] / N;
    int C4 = C / 4;                 // C=80 -> 20
    long n4 = (long)out_size / 4;

    // fork: all output zeroing on s1, concurrent with hist+prep on main stream
    cudaEventRecord(evF, 0);
    cudaStreamWaitEvent(s1, evF, 0);
    k_zero_cold<<<4096, 256, 0, s1>>>(Bp, Dp, Hp, Wp, (float4*)d_out, n4, C4);
    k_zero_hot<<<2048, 256, 0, s1>>>(Bp, Dp, Hp, Wp, (float4*)d_out, n4, C4);
    cudaEventRecord(evZ, s1);

    k_hist<<<(N + 255) / 256, 256>>>((const int4*)coords, N, Bp, Dp, Wp);
    k_prep<<<MAX_RANKS / 256, 256>>>(N, Bp, Dp, Hp, Wp);
    cudaEventRecord(evP, 0);                 // prep done: g_meta no longer needed

    // s1: reset g_meta concurrently with k_main (after prep consumed it)
    cudaStreamWaitEvent(s1, evP, 0);
    k_meta_reset<<<512, 256, 0, s1>>>();
    cudaEventRecord(evM, s1);

    // main: k_main needs prep tables + all zeroing done
    cudaStreamWaitEvent(0, evZ, 0);
    dim3 b2(C4, 16);
    k_main<<<(N + ROWS - 1) / ROWS, b2>>>(
        (const float4*)feats, (const int4*)coords, (float4*)d_out, N, C4,
        Bp, Dp, Hp, Wp);

    // join meta reset before graph end (clean state for next replay)
    cudaStreamWaitEvent(0, evM, 0);
}